// round 10
// baseline (speedup 1.0000x reference)
#include <cuda_runtime.h>
#include <cstdint>

// CosineSim3D: out[b,n,:300] = softmax_n( (a_n . sum_m b_m/|b_m|) / |a_n| )
// B=128, N=M=1024, D=300. Grid 512 = 4 quarter-blocks per batch, all
// co-resident (148 SMs x 4 slots at 256thr). Self-cleaning 4-way rendezvous;
// softmax via per-block (max,sumexp) tuples -- no score reload.

static constexpr int BATCH   = 128;
static constexpr int NROW    = 1024;
static constexpr int P       = 4;              // blocks per batch
static constexpr int QROWS   = NROW / P;       // 256 rows per block
static constexpr int DDIM    = 300;
static constexpr int NQ      = 75;             // float4 per row
static constexpr int DPAD    = 304;
static constexpr int THREADS = 256;
static constexpr int WARPS   = 8;
static constexpr int RPW     = QROWS / WARPS;  // 32 rows per warp
static constexpr int RPI     = 2;
static constexpr int GRID    = BATCH * P;      // 512 <= 148*4 = 592 slots

#define EPSV 1e-7f

// scratch + sync (zero-init at load; rendezvous protocol restores zeros)
__device__ float    g_part[BATCH][P][DPAD];
__device__ float    g_tmax[BATCH][P];      // local max
__device__ float    g_tsum[BATCH][P];      // local sumexp
__device__ unsigned g_c[BATCH][2];         // arrive counters
__device__ unsigned g_d[BATCH][2];         // passed counters

__device__ __forceinline__ float warp_sum(float v) {
    #pragma unroll
    for (int o = 16; o > 0; o >>= 1) v += __shfl_xor_sync(0xffffffffu, v, o);
    return v;
}
__device__ __forceinline__ float warp_max(float v) {
    #pragma unroll
    for (int o = 16; o > 0; o >>= 1) v = fmaxf(v, __shfl_xor_sync(0xffffffffu, v, o));
    return v;
}
__device__ __forceinline__ float dot4(float4 x, float4 y) {
    return fmaf(x.x, y.x, fmaf(x.y, y.y, fmaf(x.z, y.z, x.w * y.w)));
}
__device__ __forceinline__ void axpy4(float4& acc, float4 q, float s) {
    acc.x = fmaf(q.x, s, acc.x);
    acc.y = fmaf(q.y, s, acc.y);
    acc.z = fmaf(q.z, s, acc.z);
    acc.w = fmaf(q.w, s, acc.w);
}

// P-way rendezvous, graph-replay safe: arrive on c; spin to P; count passers
// on d; the LAST passer resets both to zero for the next replay.
__device__ __forceinline__ void rendezvous(unsigned* c, unsigned* d, int tid) {
    __threadfence();              // publish prior global writes
    __syncthreads();
    if (tid == 0) {
        atomicAdd(c, 1u);
        while (*(volatile unsigned*)c < (unsigned)P) __nanosleep(32);
        __threadfence();          // acquire peers' writes
        unsigned old = atomicAdd(d, 1u);
        if (old == (unsigned)(P - 1)) {
            atomicExch(d, 0u);
            atomicExch(c, 0u);
        }
    }
    __syncthreads();
}

__global__ void __launch_bounds__(THREADS, 4)
cosine_sim3d_kernel(const float* __restrict__ ga,
                    const float* __restrict__ gb,
                    float* __restrict__ gout)
{
    __shared__ __align__(16) float s_part[WARPS][DPAD];  // 9.7 KB
    __shared__ __align__(16) float s_bsum[DPAD];
    __shared__ float s_sc[QROWS];                        // own 256 raw scores
    __shared__ float s_red[WARPS];

    const int batch = blockIdx.x >> 2;
    const int quart = blockIdx.x & 3;
    const int tid   = threadIdx.x;
    const int wid   = tid >> 5;
    const int lane  = tid & 31;
    const bool has_q2 = lane < (NQ - 64);  // lane < 11
    const float4 f4z = make_float4(0.f, 0.f, 0.f, 0.f);

    const float4* a4 = reinterpret_cast<const float4*>(ga) + (size_t)batch * NROW * NQ;
    const float4* b4 = reinterpret_cast<const float4*>(gb) + (size_t)batch * NROW * NQ;
    float4*       o4 = reinterpret_cast<float4*>(gout)     + (size_t)batch * NROW * NQ;

    const int rbase = quart * QROWS + wid * RPW;   // first global row (this warp)

    // ========== Phase 1: partial bsum over this quarter's 256 b-rows ==========
    float4 acc0 = f4z, acc1 = f4z, acc2 = f4z;

    #pragma unroll 1
    for (int i = 0; i < RPW; i += RPI) {
        float4 q0[RPI], q1[RPI], q2[RPI];
        #pragma unroll
        for (int r = 0; r < RPI; r++) {
            const float4* row = b4 + (size_t)(rbase + i + r) * NQ;
            q0[r] = row[lane];
            q1[r] = row[lane + 32];
            q2[r] = has_q2 ? row[lane + 64] : f4z;
        }
        #pragma unroll
        for (int r = 0; r < RPI; r++) {
            float ss = dot4(q0[r], q0[r]) + dot4(q1[r], q1[r]) + dot4(q2[r], q2[r]);
            ss = warp_sum(ss);
            float inv = 1.0f / sqrtf(fmaxf(ss, EPSV));
            axpy4(acc0, q0[r], inv);
            axpy4(acc1, q1[r], inv);
            axpy4(acc2, q2[r], inv);
        }
    }

    {
        float4* p4 = reinterpret_cast<float4*>(&s_part[wid][0]);
        p4[lane]      = acc0;
        p4[lane + 32] = acc1;
        if (has_q2) p4[lane + 64] = acc2;
    }
    __syncthreads();

    for (int d = tid; d < DDIM; d += THREADS) {
        float s = 0.f;
        #pragma unroll
        for (int w = 0; w < WARPS; w++) s += s_part[w][d];
        g_part[batch][quart][d] = s;
    }

    // ========== Rendezvous 1: all four partials ready ==========
    rendezvous(&g_c[batch][0], &g_d[batch][0], tid);

    for (int d = tid; d < DDIM; d += THREADS) {
        float s = 0.f;
        #pragma unroll
        for (int p = 0; p < P; p++) s += __ldcg(&g_part[batch][p][d]);
        s_bsum[d] = s;
    }
    __syncthreads();

    float4 bs0, bs1, bs2;
    {
        const float4* bsum4 = reinterpret_cast<const float4*>(s_bsum);
        bs0 = bsum4[lane];
        bs1 = bsum4[lane + 32];
        bs2 = has_q2 ? bsum4[lane + 64] : f4z;
    }

    // ========== Phase 2: scores for this quarter's 256 a-rows ==========
    #pragma unroll 1
    for (int i = 0; i < RPW; i += RPI) {
        float4 q0[RPI], q1[RPI], q2[RPI];
        #pragma unroll
        for (int r = 0; r < RPI; r++) {
            const float4* row = a4 + (size_t)(rbase + i + r) * NQ;
            q0[r] = row[lane];
            q1[r] = row[lane + 32];
            q2[r] = has_q2 ? row[lane + 64] : f4z;
        }
        #pragma unroll
        for (int r = 0; r < RPI; r++) {
            float ss = dot4(q0[r], q0[r]) + dot4(q1[r], q1[r]) + dot4(q2[r], q2[r]);
            float dt = dot4(q0[r], bs0) + dot4(q1[r], bs1) + dot4(q2[r], bs2);
            #pragma unroll
            for (int o = 16; o > 0; o >>= 1) {
                ss += __shfl_xor_sync(0xffffffffu, ss, o);
                dt += __shfl_xor_sync(0xffffffffu, dt, o);
            }
            if (lane == 0)
                s_sc[wid * RPW + i + r] = dt / sqrtf(fmaxf(ss, EPSV));
        }
    }
    __syncthreads();

    // ---- local softmax tuple over own 256 scores (fixed order) ----
    const float v0 = s_sc[tid];
    float lmx = warp_max(v0);
    if (lane == 0) s_red[wid] = lmx;
    __syncthreads();
    if (wid == 0) {
        float m = (lane < WARPS) ? s_red[lane] : -3.4e38f;
        m = warp_max(m);
        if (lane == 0) s_red[0] = m;
    }
    __syncthreads();
    const float bmax = s_red[0];
    __syncthreads();

    float es = __expf(v0 - bmax);
    es = warp_sum(es);
    if (lane == 0) s_red[wid] = es;
    __syncthreads();
    if (wid == 0 && lane == 0) {
        g_tmax[batch][quart] = bmax;
        g_tsum[batch][quart] = s_red[0] == 0.f ? 0.f : 0.f;  // placeholder overwritten below
    }
    // recompute block sum via s_red (already written by all warps)
    if (wid == 0) {
        float s = (lane < WARPS) ? s_red[lane] : 0.f;
        s = warp_sum(s);
        if (lane == 0) {
            g_tmax[batch][quart] = bmax;
            g_tsum[batch][quart] = s;
        }
    }

    // ========== Rendezvous 2: all four tuples ready ==========
    rendezvous(&g_c[batch][1], &g_d[batch][1], tid);

    // combine tuples in fixed order -> identical result in all 4 blocks
    const float m0 = __ldcg(&g_tmax[batch][0]);
    const float m1 = __ldcg(&g_tmax[batch][1]);
    const float m2 = __ldcg(&g_tmax[batch][2]);
    const float m3 = __ldcg(&g_tmax[batch][3]);
    const float u0 = __ldcg(&g_tsum[batch][0]);
    const float u1 = __ldcg(&g_tsum[batch][1]);
    const float u2 = __ldcg(&g_tsum[batch][2]);
    const float u3 = __ldcg(&g_tsum[batch][3]);
    const float gmx = fmaxf(fmaxf(m0, m1), fmaxf(m2, m3));
    const float gsum = u0 * __expf(m0 - gmx) + u1 * __expf(m1 - gmx)
                     + u2 * __expf(m2 - gmx) + u3 * __expf(m3 - gmx);
    const float inv_sum = 1.0f / gsum;

    // ========== Phase 3: broadcast-write this quarter's 256 rows ==========
    const int lbase = wid * RPW;
    #pragma unroll 1
    for (int i = 0; i < RPW; i++) {
        const float pr = __expf(s_sc[lbase + i] - gmx) * inv_sum;
        const float4 pv = make_float4(pr, pr, pr, pr);
        float4* orow = o4 + (size_t)(rbase + i) * NQ;
        orow[lane]      = pv;
        orow[lane + 32] = pv;
        if (has_q2) orow[lane + 64] = pv;
    }
}

extern "C" void kernel_launch(void* const* d_in, const int* in_sizes, int n_in,
                              void* d_out, int out_size) {
    const float* a = (const float*)d_in[0];
    const float* b = (const float*)d_in[1];
    float* out = (float*)d_out;
    cosine_sim3d_kernel<<<GRID, THREADS>>>(a, b, out);
}

// round 11
// speedup vs baseline: 1.0118x; 1.0118x over previous
#include <cuda_runtime.h>
#include <cstdint>

// CosineSim3D: out[b,n,:300] = softmax_n( (a_n . sum_m b_m/|b_m|) / |a_n| )
// B=128, N=M=1024, D=300. Grid 256 = 2 half-blocks per batch, all co-resident.
// Scores stay in smem; halves exchange only (max,sumexp) tuples. Streaming
// output stores. Self-cleaning pair rendezvous (graph-replay safe).

static constexpr int BATCH   = 128;
static constexpr int NROW    = 1024;
static constexpr int HROWS   = 512;            // rows per half-block
static constexpr int DDIM    = 300;
static constexpr int NQ      = 75;             // float4 per row
static constexpr int DPAD    = 304;
static constexpr int THREADS = 512;
static constexpr int WARPS   = 16;
static constexpr int RPW     = HROWS / WARPS;  // 32 rows per warp
static constexpr int RPI     = 2;
static constexpr int GRID    = BATCH * 2;      // 256 <= 148*2 resident slots

#define EPSV 1e-7f

// scratch + sync (zero-init at load; protocol restores zeros every replay)
__device__ float    g_part[BATCH][2][DPAD];
__device__ float    g_tmax[BATCH][2];
__device__ float    g_tsum[BATCH][2];
__device__ unsigned g_c[BATCH][2];   // arrive counters
__device__ unsigned g_d[BATCH][2];   // passed counters

__device__ __forceinline__ float warp_sum(float v) {
    #pragma unroll
    for (int o = 16; o > 0; o >>= 1) v += __shfl_xor_sync(0xffffffffu, v, o);
    return v;
}
__device__ __forceinline__ float warp_max(float v) {
    #pragma unroll
    for (int o = 16; o > 0; o >>= 1) v = fmaxf(v, __shfl_xor_sync(0xffffffffu, v, o));
    return v;
}
__device__ __forceinline__ float dot4(float4 x, float4 y) {
    return fmaf(x.x, y.x, fmaf(x.y, y.y, fmaf(x.z, y.z, x.w * y.w)));
}
__device__ __forceinline__ void axpy4(float4& acc, float4 q, float s) {
    acc.x = fmaf(q.x, s, acc.x);
    acc.y = fmaf(q.y, s, acc.y);
    acc.z = fmaf(q.z, s, acc.z);
    acc.w = fmaf(q.w, s, acc.w);
}

// Pair rendezvous, graph-replay safe: arrive on c; spin to 2; count passers on
// d; the SECOND passer resets both to zero for the next replay.
__device__ __forceinline__ void pair_rendezvous(unsigned* c, unsigned* d, int tid) {
    __threadfence();          // publish this block's prior global writes
    __syncthreads();
    if (tid == 0) {
        atomicAdd(c, 1u);
        while (*(volatile unsigned*)c < 2u) __nanosleep(32);
        __threadfence();      // acquire partner's writes
        unsigned old = atomicAdd(d, 1u);
        if (old == 1u) {
            atomicExch(d, 0u);
            atomicExch(c, 0u);
        }
    }
    __syncthreads();
}

__global__ void __launch_bounds__(THREADS, 2)
cosine_sim3d_kernel(const float* __restrict__ ga,
                    const float* __restrict__ gb,
                    float* __restrict__ gout)
{
    __shared__ __align__(16) float s_part[WARPS][DPAD];  // 19.5 KB
    __shared__ __align__(16) float s_bsum[DPAD];
    __shared__ float s_sc[HROWS];                        // own half's raw scores
    __shared__ float s_red[WARPS];

    const int batch = blockIdx.x >> 1;
    const int half  = blockIdx.x & 1;
    const int tid   = threadIdx.x;
    const int wid   = tid >> 5;
    const int lane  = tid & 31;
    const bool has_q2 = lane < (NQ - 64);  // lane < 11
    const float4 f4z = make_float4(0.f, 0.f, 0.f, 0.f);

    const float4* a4 = reinterpret_cast<const float4*>(ga) + (size_t)batch * NROW * NQ;
    const float4* b4 = reinterpret_cast<const float4*>(gb) + (size_t)batch * NROW * NQ;
    float4*       o4 = reinterpret_cast<float4*>(gout)     + (size_t)batch * NROW * NQ;

    const int rbase = half * HROWS + wid * RPW;   // first global row (this warp)

    // ========== Phase 1: partial bsum over this half's 512 b-rows ==========
    float4 acc0 = f4z, acc1 = f4z, acc2 = f4z;

    #pragma unroll 1
    for (int i = 0; i < RPW; i += RPI) {
        float4 q0[RPI], q1[RPI], q2[RPI];
        #pragma unroll
        for (int r = 0; r < RPI; r++) {
            const float4* row = b4 + (size_t)(rbase + i + r) * NQ;
            q0[r] = __ldcs(row + lane);
            q1[r] = __ldcs(row + lane + 32);
            q2[r] = has_q2 ? __ldcs(row + lane + 64) : f4z;
        }
        #pragma unroll
        for (int r = 0; r < RPI; r++) {
            float ss = dot4(q0[r], q0[r]) + dot4(q1[r], q1[r]) + dot4(q2[r], q2[r]);
            ss = warp_sum(ss);
            float inv = 1.0f / sqrtf(fmaxf(ss, EPSV));
            axpy4(acc0, q0[r], inv);
            axpy4(acc1, q1[r], inv);
            axpy4(acc2, q2[r], inv);
        }
    }

    {
        float4* p4 = reinterpret_cast<float4*>(&s_part[wid][0]);
        p4[lane]      = acc0;
        p4[lane + 32] = acc1;
        if (has_q2) p4[lane + 64] = acc2;
    }
    __syncthreads();

    if (tid < DDIM) {
        float s = 0.f;
        #pragma unroll
        for (int w = 0; w < WARPS; w++) s += s_part[w][tid];
        g_part[batch][half][tid] = s;
    }

    // ========== Rendezvous 1: both halves' partials ready ==========
    pair_rendezvous(&g_c[batch][0], &g_d[batch][0], tid);

    if (tid < DDIM)
        s_bsum[tid] = __ldcg(&g_part[batch][0][tid]) + __ldcg(&g_part[batch][1][tid]);
    __syncthreads();

    float4 bs0, bs1, bs2;
    {
        const float4* bsum4 = reinterpret_cast<const float4*>(s_bsum);
        bs0 = bsum4[lane];
        bs1 = bsum4[lane + 32];
        bs2 = has_q2 ? bsum4[lane + 64] : f4z;
    }

    // ========== Phase 2: scores for this half's 512 a-rows (smem only) ======
    #pragma unroll 1
    for (int i = 0; i < RPW; i += RPI) {
        float4 q0[RPI], q1[RPI], q2[RPI];
        #pragma unroll
        for (int r = 0; r < RPI; r++) {
            const float4* row = a4 + (size_t)(rbase + i + r) * NQ;
            q0[r] = __ldcs(row + lane);
            q1[r] = __ldcs(row + lane + 32);
            q2[r] = has_q2 ? __ldcs(row + lane + 64) : f4z;
        }
        #pragma unroll
        for (int r = 0; r < RPI; r++) {
            float ss = dot4(q0[r], q0[r]) + dot4(q1[r], q1[r]) + dot4(q2[r], q2[r]);
            float dt = dot4(q0[r], bs0) + dot4(q1[r], bs1) + dot4(q2[r], bs2);
            #pragma unroll
            for (int o = 16; o > 0; o >>= 1) {
                ss += __shfl_xor_sync(0xffffffffu, ss, o);
                dt += __shfl_xor_sync(0xffffffffu, dt, o);
            }
            if (lane == 0)
                s_sc[wid * RPW + i + r] = dt / sqrtf(fmaxf(ss, EPSV));
        }
    }
    __syncthreads();

    // ---- local softmax tuple over own 512 scores (fixed order) ----
    float lmx = warp_max(s_sc[tid]);
    if (lane == 0) s_red[wid] = lmx;
    __syncthreads();
    if (wid == 0) {
        float m = (lane < WARPS) ? s_red[lane] : -3.4e38f;
        m = warp_max(m);
        if (lane == 0) s_red[0] = m;
    }
    __syncthreads();
    const float bmax = s_red[0];
    __syncthreads();

    float es = __expf(s_sc[tid] - bmax);
    es = warp_sum(es);
    if (lane == 0) s_red[wid] = es;
    __syncthreads();
    if (wid == 0) {
        float s = (lane < WARPS) ? s_red[lane] : 0.f;
        s = warp_sum(s);
        if (lane == 0) {
            g_tmax[batch][half] = bmax;
            g_tsum[batch][half] = s;
        }
    }

    // ========== Rendezvous 2: both tuples ready ==========
    pair_rendezvous(&g_c[batch][1], &g_d[batch][1], tid);

    // combine tuples in fixed order -> identical in both halves
    const float m0 = __ldcg(&g_tmax[batch][0]);
    const float m1 = __ldcg(&g_tmax[batch][1]);
    const float u0 = __ldcg(&g_tsum[batch][0]);
    const float u1 = __ldcg(&g_tsum[batch][1]);
    const float gmx  = fmaxf(m0, m1);
    const float gsum = u0 * __expf(m0 - gmx) + u1 * __expf(m1 - gmx);
    const float inv_sum = 1.0f / gsum;

    // ========== Phase 3: broadcast-write this half's 512 rows ==========
    const int lbase = wid * RPW;
    #pragma unroll 1
    for (int i = 0; i < RPW; i++) {
        const float pr = __expf(s_sc[lbase + i] - gmx) * inv_sum;
        const float4 pv = make_float4(pr, pr, pr, pr);
        float4* orow = o4 + (size_t)(half * HROWS + lbase + i) * NQ;
        __stcs(orow + lane,      pv);
        __stcs(orow + lane + 32, pv);
        if (has_q2) __stcs(orow + lane + 64, pv);
    }
}

extern "C" void kernel_launch(void* const* d_in, const int* in_sizes, int n_in,
                              void* d_out, int out_size) {
    const float* a = (const float*)d_in[0];
    const float* b = (const float*)d_in[1];
    float* out = (float*)d_out;
    cosine_sim3d_kernel<<<GRID, THREADS>>>(a, b, out);
}

// round 12
// speedup vs baseline: 1.0341x; 1.0221x over previous
#include <cuda_runtime.h>

// CosineSim3D: out[b,n,:300] = softmax_n( (a_n . sum_m b_m/|b_m|) / |a_n| )
// B=128, N=M=1024, D=300. Single fused kernel, 1 block per batch, 1024 thr.
// Device time sits at the 471MB memory floor; streaming cache hints (ldcs/stcs)
// minimize L2 dirty-line carryover between graph replays.

static constexpr int BATCH   = 128;
static constexpr int NROW    = 1024;
static constexpr int DDIM    = 300;
static constexpr int NQ      = 75;   // float4 per row (300 floats)
static constexpr int DPAD    = 304;  // padded feature dim
static constexpr int THREADS = 1024;
static constexpr int WARPS   = 32;
static constexpr int RPW     = NROW / WARPS;  // 32 rows per warp
static constexpr int RPI     = 2;             // rows per load-batch

#define EPSV 1e-7f

__device__ __forceinline__ float warp_sum(float v) {
    #pragma unroll
    for (int o = 16; o > 0; o >>= 1) v += __shfl_xor_sync(0xffffffffu, v, o);
    return v;
}
__device__ __forceinline__ float warp_max(float v) {
    #pragma unroll
    for (int o = 16; o > 0; o >>= 1) v = fmaxf(v, __shfl_xor_sync(0xffffffffu, v, o));
    return v;
}
__device__ __forceinline__ float dot4(float4 x, float4 y) {
    return fmaf(x.x, y.x, fmaf(x.y, y.y, fmaf(x.z, y.z, x.w * y.w)));
}
__device__ __forceinline__ void axpy4(float4& acc, float4 q, float s) {
    acc.x = fmaf(q.x, s, acc.x);
    acc.y = fmaf(q.y, s, acc.y);
    acc.z = fmaf(q.z, s, acc.z);
    acc.w = fmaf(q.w, s, acc.w);
}

__global__ void __launch_bounds__(THREADS, 1)
cosine_sim3d_kernel(const float* __restrict__ ga,
                    const float* __restrict__ gb,
                    float* __restrict__ gout)
{
    __shared__ __align__(16) float s_part[WARPS][DPAD];  // 38.9 KB
    __shared__ __align__(16) float s_bsum[DPAD];
    __shared__ float s_scores[NROW];
    __shared__ float s_red[WARPS];

    const int batch = blockIdx.x;
    const int tid   = threadIdx.x;
    const int wid   = tid >> 5;
    const int lane  = tid & 31;
    const bool has_q2 = lane < (NQ - 64);  // lane < 11

    const float4* a4 = reinterpret_cast<const float4*>(ga) + (size_t)batch * NROW * NQ;
    const float4* b4 = reinterpret_cast<const float4*>(gb) + (size_t)batch * NROW * NQ;
    float4*       o4 = reinterpret_cast<float4*>(gout)     + (size_t)batch * NROW * NQ;

    const int rbase = wid * RPW;
    const float4 f4z = make_float4(0.f, 0.f, 0.f, 0.f);

    // ---------------- Phase 1: bsum = sum_m b[m,:] / ||b[m,:]|| ----------------
    float4 acc0 = f4z, acc1 = f4z, acc2 = f4z;

    #pragma unroll 1
    for (int i = 0; i < RPW; i += RPI) {
        float4 q0[RPI], q1[RPI], q2[RPI];
        #pragma unroll
        for (int r = 0; r < RPI; r++) {
            const float4* row = b4 + (size_t)(rbase + i + r) * NQ;
            q0[r] = __ldcs(row + lane);
            q1[r] = __ldcs(row + lane + 32);
            q2[r] = has_q2 ? __ldcs(row + lane + 64) : f4z;
        }
        #pragma unroll
        for (int r = 0; r < RPI; r++) {
            float ss = dot4(q0[r], q0[r]) + dot4(q1[r], q1[r]) + dot4(q2[r], q2[r]);
            ss = warp_sum(ss);
            float inv = 1.0f / sqrtf(fmaxf(ss, EPSV));
            axpy4(acc0, q0[r], inv);
            axpy4(acc1, q1[r], inv);
            axpy4(acc2, q2[r], inv);
        }
    }

    {
        float4* p4 = reinterpret_cast<float4*>(&s_part[wid][0]);
        p4[lane]      = acc0;
        p4[lane + 32] = acc1;
        if (has_q2) p4[lane + 64] = acc2;
    }
    __syncthreads();

    // deterministic cross-warp reduction (300 < 1024 threads)
    if (tid < DDIM) {
        float s = 0.f;
        #pragma unroll
        for (int w = 0; w < WARPS; w++) s += s_part[w][tid];
        s_bsum[tid] = s;
    }
    __syncthreads();

    // ---------------- Phase 2: scores[n] = (a_n . bsum) / ||a_n|| ----------------
    float4 bs0, bs1, bs2;
    {
        const float4* bsum4 = reinterpret_cast<const float4*>(s_bsum);
        bs0 = bsum4[lane];
        bs1 = bsum4[lane + 32];
        bs2 = has_q2 ? bsum4[lane + 64] : f4z;
    }

    #pragma unroll 1
    for (int i = 0; i < RPW; i += RPI) {
        float4 q0[RPI], q1[RPI], q2[RPI];
        #pragma unroll
        for (int r = 0; r < RPI; r++) {
            const float4* row = a4 + (size_t)(rbase + i + r) * NQ;
            q0[r] = __ldcs(row + lane);
            q1[r] = __ldcs(row + lane + 32);
            q2[r] = has_q2 ? __ldcs(row + lane + 64) : f4z;
        }
        #pragma unroll
        for (int r = 0; r < RPI; r++) {
            float ss = dot4(q0[r], q0[r]) + dot4(q1[r], q1[r]) + dot4(q2[r], q2[r]);
            float dt = dot4(q0[r], bs0) + dot4(q1[r], bs1) + dot4(q2[r], bs2);
            #pragma unroll
            for (int o = 16; o > 0; o >>= 1) {
                ss += __shfl_xor_sync(0xffffffffu, ss, o);
                dt += __shfl_xor_sync(0xffffffffu, dt, o);
            }
            if (lane == 0)
                s_scores[rbase + i + r] = dt / sqrtf(fmaxf(ss, EPSV));
        }
    }
    __syncthreads();

    // ---------------- Phase 3: softmax over n (per batch) ----------------
    float v0 = s_scores[tid];  // 1024 threads, 1 score each

    float mx = warp_max(v0);
    if (lane == 0) s_red[wid] = mx;
    __syncthreads();
    if (wid == 0) {
        float m = s_red[lane];           // WARPS == 32 == lanes
        m = warp_max(m);
        if (lane == 0) s_red[0] = m;
    }
    __syncthreads();
    const float gmx = s_red[0];
    __syncthreads();  // all reads of s_red[0] done before reuse

    float e0 = __expf(v0 - gmx);
    float sm = warp_sum(e0);
    if (lane == 0) s_red[wid] = sm;
    __syncthreads();
    if (wid == 0) {
        float s = s_red[lane];
        s = warp_sum(s);
        if (lane == 0) s_red[0] = s;
    }
    __syncthreads();
    const float inv_sum = 1.0f / s_red[0];

    s_scores[tid] = e0 * inv_sum;
    __syncthreads();

    // ---------------- Phase 4: tiled broadcast write (streaming stores) --------
    #pragma unroll 1
    for (int i = 0; i < RPW; i++) {
        const int row = rbase + i;
        const float p = s_scores[row];
        const float4 v = make_float4(p, p, p, p);
        float4* orow = o4 + (size_t)row * NQ;
        __stcs(orow + lane,      v);
        __stcs(orow + lane + 32, v);
        if (has_q2) __stcs(orow + lane + 64, v);
    }
}

extern "C" void kernel_launch(void* const* d_in, const int* in_sizes, int n_in,
                              void* d_out, int out_size) {
    const float* a = (const float*)d_in[0];
    const float* b = (const float*)d_in[1];
    float* out = (float*)d_out;
    cosine_sim3d_kernel<<<BATCH, THREADS>>>(a, b, out);
}